// round 15
// baseline (speedup 1.0000x reference)
#include <cuda_runtime.h>
#include <cuda_bf16.h>
#include <math.h>

#define Bc 4
#define Sc 1024
#define Dc 1024
#define Ec 8
#define DEc 128
#define SCALEF (1.0f/32.0f)   // 1/sqrt(1024)
#define QPITCH 136            // bf16 row pitch in k_score (conflict-free)
#define OPITCH 72             // bf16 row pitch in k_out (conflict-free)

// -------- scratch (static __device__, allocation-free) --------
__device__ float g_S[(size_t)Ec*Bc*Sc*Sc];           // unnormalized exp scores
__device__ float g_L[Ec*Bc*Sc];                      // row sumexp
__device__ __nv_bfloat16 g_Ah[(size_t)Bc*Sc*Sc];     // attn hi
__device__ __nv_bfloat16 g_Al[(size_t)Bc*Sc*Sc];     // attn lo
__device__ __nv_bfloat16 g_vt_h[Bc*2*DEc*Sc];        // V^T hi  [b][slot][col][t]
__device__ __nv_bfloat16 g_vt_l[Bc*2*DEc*Sc];        // V^T lo

// ---- bf16 helpers ----
__device__ __forceinline__ unsigned pkbf2(float a, float b) {
    __nv_bfloat162 t = __floats2bfloat162_rn(a, b);
    return *(unsigned*)&t;
}
__device__ __forceinline__ void split2(float x, float y,
                                       unsigned &hi, unsigned &lo) {
    __nv_bfloat16 hx = __float2bfloat16(x), hy = __float2bfloat16(y);
    float rx = x - __bfloat162float(hx), ry = y - __bfloat162float(hy);
    __nv_bfloat162 h; h.x = hx; h.y = hy;
    hi = *(unsigned*)&h;
    lo = pkbf2(rx, ry);
}
__device__ __forceinline__ void split1(float x, __nv_bfloat16 &hi, __nv_bfloat16 &lo) {
    hi = __float2bfloat16(x);
    lo = __float2bfloat16(x - __bfloat162float(hi));
}
__device__ __forceinline__ void mma_bf16(float acc[4],
                                         unsigned a0, unsigned a1, unsigned a2, unsigned a3,
                                         unsigned b0, unsigned b1) {
    asm volatile(
        "mma.sync.aligned.m16n8k16.row.col.f32.bf16.bf16.f32 "
        "{%0,%1,%2,%3}, {%4,%5,%6,%7}, {%8,%9}, {%0,%1,%2,%3};"
        : "+f"(acc[0]), "+f"(acc[1]), "+f"(acc[2]), "+f"(acc[3])
        : "r"(a0), "r"(a1), "r"(a2), "r"(a3), "r"(b0), "r"(b1));
}

// inline top-2 (first-occurrence ties, like lax.top_k); every thread computes
__device__ __forceinline__ void top2_inline(const float* __restrict__ rp, int b,
                                            int &i1, int &i2) {
    i1 = 0; float v1 = rp[b*Ec];
    #pragma unroll
    for (int e = 1; e < Ec; e++) {
        float v = rp[b*Ec + e];
        if (v > v1) { v1 = v; i1 = e; }
    }
    i2 = -1; float v2 = -INFINITY;
    #pragma unroll
    for (int e = 0; e < Ec; e++) {
        if (e == i1) continue;
        float v = rp[b*Ec + e];
        if (v > v2) { v2 = v; i2 = e; }
    }
}

// ============================================================
// Kz: zero the whole output.
// ============================================================
__global__ void k_zero(float* __restrict__ out) {
    size_t i = ((size_t)blockIdx.x*256 + threadIdx.x)*4;
    *(float4*)(out + i) = make_float4(0.f, 0.f, 0.f, 0.f);
}

// ============================================================
// Kv: V-slice -> transposed bf16 hi/lo [b][slot][col][t].
// ============================================================
__global__ void k_vprep(const float* __restrict__ Vg, const float* __restrict__ rp) {
    const int bs = blockIdx.x;            // b*2 + slot
    const int b = bs >> 1, slot = bs & 1;
    int i1, i2; top2_inline(rp, b, i1, i2);
    const int e = slot ? i2 : i1;
    const int t0 = blockIdx.y * 64;
    const int tid = threadIdx.x;

    __shared__ __nv_bfloat16 sh[128*OPITCH];
    __shared__ __nv_bfloat16 sl[128*OPITCH];

    const float* Vb = Vg + ((size_t)b*Sc + t0)*Dc + e*DEc;
    for (int l = tid; l < 2048; l += 256) {
        int t = l >> 5, c4 = (l & 31)*4;
        float4 v = *(const float4*)(Vb + (size_t)t*Dc + c4);
        __nv_bfloat16 h, lo;
        split1(v.x, h, lo); sh[(c4  )*OPITCH + t] = h; sl[(c4  )*OPITCH + t] = lo;
        split1(v.y, h, lo); sh[(c4+1)*OPITCH + t] = h; sl[(c4+1)*OPITCH + t] = lo;
        split1(v.z, h, lo); sh[(c4+2)*OPITCH + t] = h; sl[(c4+2)*OPITCH + t] = lo;
        split1(v.w, h, lo); sh[(c4+3)*OPITCH + t] = h; sl[(c4+3)*OPITCH + t] = lo;
    }
    __syncthreads();
    __nv_bfloat16* Dh = g_vt_h + ((size_t)bs*DEc)*Sc + t0;
    __nv_bfloat16* Dl = g_vt_l + ((size_t)bs*DEc)*Sc + t0;
    for (int l = tid; l < 2048; l += 256) {
        int col = l >> 4, tq = (l & 15)*4;
        *(uint2*)(Dh + (size_t)col*Sc + tq) = *(uint2*)(sh + col*OPITCH + tq);
        *(uint2*)(Dl + (size_t)col*Sc + tq) = *(uint2*)(sl + col*OPITCH + tq);
    }
}

// ============================================================
// K1: scores via bf16-split MMA. 128 threads = 4 warps of 32x32
// tiles (2 row-blocks x 2 col-blocks over 64x64): 32 smem wavefronts
// per 24 MMAs (was 2.0 wf/MMA with 16x32 warps).
// ============================================================
__global__ void k_score(const float* __restrict__ Qg, const float* __restrict__ Kg,
                        const int* __restrict__ em) {
    const int e = blockIdx.z, b = blockIdx.y, s0 = blockIdx.x * 64;
    if (em[e*Bc + b] == 0) return;

    extern __shared__ char smraw[];
    __nv_bfloat16* sQh = (__nv_bfloat16*)smraw;        // 64*136
    __nv_bfloat16* sQl = sQh + 64*QPITCH;
    __nv_bfloat16* sKh = sQl + 64*QPITCH;
    __nv_bfloat16* sKl = sKh + 64*QPITCH;
    float* sS  = (float*)(sKl + 64*QPITCH);            // 64*68
    float* sLp = sS + 64*68;                           // 2*64

    const int tid = threadIdx.x;
    const int w = tid >> 5, lane = tid & 31;
    const int g = lane >> 2, tig = lane & 3;
    const int rb = (w & 1) * 32, nb = (w >> 1) * 32;

    const float* Qb = Qg + ((size_t)b*Sc + s0)*Dc + e*DEc;
    for (int l = tid; l < 2048; l += 128) {
        int r = l >> 5, c = (l & 31) * 4;
        float4 v = *(const float4*)(Qb + (size_t)r*Dc + c);
        unsigned h01, l01, h23, l23;
        split2(v.x, v.y, h01, l01);
        split2(v.z, v.w, h23, l23);
        *(uint2*)(sQh + r*QPITCH + c) = make_uint2(h01, h23);
        *(uint2*)(sQl + r*QPITCH + c) = make_uint2(l01, l23);
    }

    float rs[2][2] = {};
    float* Srow = g_S + (((size_t)e*Bc + b)*Sc + s0)*Sc;

    for (int t0 = 0; t0 < Sc; t0 += 64) {
        __syncthreads();
        const float* Kb = Kg + ((size_t)b*Sc + t0)*Dc + e*DEc;
        for (int l = tid; l < 2048; l += 128) {
            int r = l >> 5, c = (l & 31) * 4;
            float4 v = *(const float4*)(Kb + (size_t)r*Dc + c);
            unsigned h01, l01, h23, l23;
            split2(v.x, v.y, h01, l01);
            split2(v.z, v.w, h23, l23);
            *(uint2*)(sKh + r*QPITCH + c) = make_uint2(h01, h23);
            *(uint2*)(sKl + r*QPITCH + c) = make_uint2(l01, l23);
        }
        __syncthreads();

        float acc[2][4][4] = {};
        #pragma unroll
        for (int kc = 0; kc < 8; kc++) {
            const int k0 = kc*16 + tig*2;
            unsigned ah[2][4], al[2][4];
            #pragma unroll
            for (int mi = 0; mi < 2; mi++) {
                const int r0 = rb + mi*16 + g;
                ah[mi][0] = *(unsigned*)(sQh + (r0  )*QPITCH + k0);
                ah[mi][1] = *(unsigned*)(sQh + (r0+8)*QPITCH + k0);
                ah[mi][2] = *(unsigned*)(sQh + (r0  )*QPITCH + k0 + 8);
                ah[mi][3] = *(unsigned*)(sQh + (r0+8)*QPITCH + k0 + 8);
                al[mi][0] = *(unsigned*)(sQl + (r0  )*QPITCH + k0);
                al[mi][1] = *(unsigned*)(sQl + (r0+8)*QPITCH + k0);
                al[mi][2] = *(unsigned*)(sQl + (r0  )*QPITCH + k0 + 8);
                al[mi][3] = *(unsigned*)(sQl + (r0+8)*QPITCH + k0 + 8);
            }
            #pragma unroll
            for (int ns = 0; ns < 4; ns++) {
                const int n = nb + ns*8 + g;
                unsigned bh0 = *(unsigned*)(sKh + n*QPITCH + k0);
                unsigned bh1 = *(unsigned*)(sKh + n*QPITCH + k0 + 8);
                unsigned bl0 = *(unsigned*)(sKl + n*QPITCH + k0);
                unsigned bl1 = *(unsigned*)(sKl + n*QPITCH + k0 + 8);
                #pragma unroll
                for (int mi = 0; mi < 2; mi++) {
                    mma_bf16(acc[mi][ns], ah[mi][0], ah[mi][1], ah[mi][2], ah[mi][3], bh0, bh1);
                    mma_bf16(acc[mi][ns], ah[mi][0], ah[mi][1], ah[mi][2], ah[mi][3], bl0, bl1);
                    mma_bf16(acc[mi][ns], al[mi][0], al[mi][1], al[mi][2], al[mi][3], bh0, bh1);
                }
            }
        }

        #pragma unroll
        for (int mi = 0; mi < 2; mi++) {
            const int r0 = rb + mi*16 + g;
            #pragma unroll
            for (int ns = 0; ns < 4; ns++) {
                float p0 = __expf(acc[mi][ns][0]*SCALEF);
                float p1 = __expf(acc[mi][ns][1]*SCALEF);
                float p2 = __expf(acc[mi][ns][2]*SCALEF);
                float p3 = __expf(acc[mi][ns][3]*SCALEF);
                rs[mi][0] += p0 + p1;
                rs[mi][1] += p2 + p3;
                const int col = nb + ns*8 + tig*2;
                *(float2*)(sS + (r0  )*68 + col) = make_float2(p0, p1);
                *(float2*)(sS + (r0+8)*68 + col) = make_float2(p2, p3);
            }
        }
        __syncthreads();

        for (int l = tid; l < 1024; l += 128) {
            int r = l >> 4, c4 = l & 15;
            *(float4*)(Srow + (size_t)r*Sc + t0 + c4*4) = *(const float4*)(sS + r*68 + c4*4);
        }
    }

    #pragma unroll
    for (int mi = 0; mi < 2; mi++)
        #pragma unroll
        for (int j = 0; j < 2; j++) {
            rs[mi][j] += __shfl_xor_sync(0xffffffffu, rs[mi][j], 1);
            rs[mi][j] += __shfl_xor_sync(0xffffffffu, rs[mi][j], 2);
        }
    if (tig == 0) {
        #pragma unroll
        for (int mi = 0; mi < 2; mi++) {
            sLp[(w >> 1)*64 + rb + mi*16 + g]     = rs[mi][0];
            sLp[(w >> 1)*64 + rb + mi*16 + g + 8] = rs[mi][1];
        }
    }
    __syncthreads();
    if (tid < 64)
        g_L[(e*Bc + b)*Sc + s0 + tid] = sLp[tid] + sLp[64 + tid];
}

// ============================================================
// K2: attn = sum_e mask*p/L, bf16 hi/lo emit. 2 rows per block.
// ============================================================
__global__ void k_combine(const int* __restrict__ em) {
    const int blk = blockIdx.x;                 // b*512 + spair
    const int b = blk >> 9, s0 = (blk & 511)*2;
    const int tid = threadIdx.x;

    float4 acc0 = make_float4(0.f, 0.f, 0.f, 0.f);
    float4 acc1 = make_float4(0.f, 0.f, 0.f, 0.f);
    #pragma unroll
    for (int e = 0; e < Ec; e++) {
        if (em[e*Bc + b] == 0) continue;
        int eb = e*Bc + b;
        float iL0 = 1.0f / g_L[(size_t)eb*Sc + s0];
        float iL1 = 1.0f / g_L[(size_t)eb*Sc + s0 + 1];
        const float* base = g_S + ((size_t)eb*Sc + s0)*Sc + tid*4;
        float4 v0 = *(const float4*)(base);
        float4 v1 = *(const float4*)(base + Sc);
        acc0.x += v0.x*iL0; acc0.y += v0.y*iL0; acc0.z += v0.z*iL0; acc0.w += v0.w*iL0;
        acc1.x += v1.x*iL1; acc1.y += v1.y*iL1; acc1.z += v1.z*iL1; acc1.w += v1.w*iL1;
    }
    unsigned h01, l01, h23, l23;
    size_t ob = ((size_t)b*Sc + s0)*Sc + tid*4;
    split2(acc0.x, acc0.y, h01, l01);
    split2(acc0.z, acc0.w, h23, l23);
    *(uint2*)(g_Ah + ob) = make_uint2(h01, h23);
    *(uint2*)(g_Al + ob) = make_uint2(l01, l23);
    split2(acc1.x, acc1.y, h01, l01);
    split2(acc1.z, acc1.w, h23, l23);
    *(uint2*)(g_Ah + ob + Sc) = make_uint2(h01, h23);
    *(uint2*)(g_Al + ob + Sc) = make_uint2(l01, l23);
}

// ============================================================
// K3: out = attn @ V-slice. 128 threads = 4 warps of 32x32 tiles
// over a 32x128 block tile (A rows shared by all warps).
// grid (B, 32, 2 slots) = 256 working blocks.
// ============================================================
__global__ void k_out(const float* __restrict__ rp, float* __restrict__ out) {
    const int b = blockIdx.x, s0 = blockIdx.y*32, slot = blockIdx.z;
    int i1, i2; top2_inline(rp, b, i1, i2);
    const int e = slot ? i2 : i1;
    const int bs = b*2 + slot;

    extern __shared__ __nv_bfloat16 smb[];
    __nv_bfloat16* sAh = smb;                  // 32*72
    __nv_bfloat16* sAl = sAh + 32*OPITCH;
    __nv_bfloat16* sVh = sAl + 32*OPITCH;      // 128*72
    __nv_bfloat16* sVl = sVh + 128*OPITCH;

    const int tid = threadIdx.x;
    const int w = tid >> 5, lane = tid & 31;
    const int g = lane >> 2, tig = lane & 3;
    const int nb = w * 32;

    float acc[2][4][4] = {};

    for (int t0 = 0; t0 < Sc; t0 += 64) {
        __syncthreads();
        const __nv_bfloat16* Abh = g_Ah + ((size_t)b*Sc + s0)*Sc + t0;
        const __nv_bfloat16* Abl = g_Al + ((size_t)b*Sc + s0)*Sc + t0;
        for (int l = tid; l < 256; l += 128) {       // 32 rows x 8 uint4
            int r = l >> 3, c = (l & 7)*8;
            *(uint4*)(sAh + r*OPITCH + c) = *(const uint4*)(Abh + (size_t)r*Sc + c);
            *(uint4*)(sAl + r*OPITCH + c) = *(const uint4*)(Abl + (size_t)r*Sc + c);
        }
        const __nv_bfloat16* Vbh = g_vt_h + ((size_t)bs*DEc)*Sc + t0;
        const __nv_bfloat16* Vbl = g_vt_l + ((size_t)bs*DEc)*Sc + t0;
        for (int l = tid; l < 1024; l += 128) {      // 128 cols x 8 uint4
            int col = l >> 3, c = (l & 7)*8;
            *(uint4*)(sVh + col*OPITCH + c) = *(const uint4*)(Vbh + (size_t)col*Sc + c);
            *(uint4*)(sVl + col*OPITCH + c) = *(const uint4*)(Vbl + (size_t)col*Sc + c);
        }
        __syncthreads();

        #pragma unroll
        for (int ks = 0; ks < 4; ks++) {
            const int k0 = ks*16 + tig*2;
            unsigned ah[2][4], al[2][4];
            #pragma unroll
            for (int mi = 0; mi < 2; mi++) {
                const int r0 = mi*16 + g;
                ah[mi][0] = *(unsigned*)(sAh + (r0  )*OPITCH + k0);
                ah[mi][1] = *(unsigned*)(sAh + (r0+8)*OPITCH + k0);
                ah[mi][2] = *(unsigned*)(sAh + (r0  )*OPITCH + k0 + 8);
                ah[mi][3] = *(unsigned*)(sAh + (r0+8)*OPITCH + k0 + 8);
                al[mi][0] = *(unsigned*)(sAl + (r0  )*OPITCH + k0);
                al[mi][1] = *(unsigned*)(sAl + (r0+8)*OPITCH + k0);
                al[mi][2] = *(unsigned*)(sAl + (r0  )*OPITCH + k0 + 8);
                al[mi][3] = *(unsigned*)(sAl + (r0+8)*OPITCH + k0 + 8);
            }
            #pragma unroll
            for (int ns = 0; ns < 4; ns++) {
                const int n = nb + ns*8 + g;
                unsigned bh0 = *(unsigned*)(sVh + n*OPITCH + k0);
                unsigned bh1 = *(unsigned*)(sVh + n*OPITCH + k0 + 8);
                unsigned bl0 = *(unsigned*)(sVl + n*OPITCH + k0);
                unsigned bl1 = *(unsigned*)(sVl + n*OPITCH + k0 + 8);
                #pragma unroll
                for (int mi = 0; mi < 2; mi++) {
                    mma_bf16(acc[mi][ns], ah[mi][0], ah[mi][1], ah[mi][2], ah[mi][3], bh0, bh1);
                    mma_bf16(acc[mi][ns], ah[mi][0], ah[mi][1], ah[mi][2], ah[mi][3], bl0, bl1);
                    mma_bf16(acc[mi][ns], al[mi][0], al[mi][1], al[mi][2], al[mi][3], bh0, bh1);
                }
            }
        }
    }

    float* O = out + ((size_t)b*Sc + s0)*Dc + e*DEc;
    #pragma unroll
    for (int mi = 0; mi < 2; mi++)
        #pragma unroll
        for (int ns = 0; ns < 4; ns++) {
            const int nc = nb + ns*8 + tig*2;
            *(float2*)(O + (size_t)(mi*16+g  )*Dc + nc) = make_float2(acc[mi][ns][0], acc[mi][ns][1]);
            *(float2*)(O + (size_t)(mi*16+g+8)*Dc + nc) = make_float2(acc[mi][ns][2], acc[mi][ns][3]);
        }
}

// ============================================================
extern "C" void kernel_launch(void* const* d_in, const int* in_sizes, int n_in,
                              void* d_out, int out_size) {
    const float* Q  = (const float*)d_in[0];
    const float* K  = (const float*)d_in[1];
    const float* V  = (const float*)d_in[2];
    const float* rp = (const float*)d_in[3];
    const int*   em = (const int*)  d_in[4];
    float* out = (float*)d_out;

    const int smem_score = 4*64*QPITCH*2 + (64*68 + 2*64)*4;  // 87552 B
    const int smem_out   = (2*32 + 2*128)*OPITCH*2;           // 46080 B
    cudaFuncSetAttribute(k_score, cudaFuncAttributeMaxDynamicSharedMemorySize, smem_score);
    cudaFuncSetAttribute(k_out,   cudaFuncAttributeMaxDynamicSharedMemorySize, smem_out);

    k_zero   <<<(Bc*Sc*Dc)/(256*4), 256>>>(out);
    k_vprep  <<<dim3(Bc*2, 16), 256>>>(V, rp);
    k_score  <<<dim3(Sc/64, Bc, Ec), 128, smem_score>>>(Q, K, em);
    k_combine<<<Bc*Sc/2, 256>>>(em);
    k_out    <<<dim3(Bc, Sc/32, 2), 128, smem_out>>>(rp, out);
}

// round 16
// speedup vs baseline: 1.1566x; 1.1566x over previous
#include <cuda_runtime.h>
#include <cuda_bf16.h>
#include <math.h>

#define Bc 4
#define Sc 1024
#define Dc 1024
#define Ec 8
#define DEc 128
#define SCALEF (1.0f/32.0f)   // 1/sqrt(1024)
#define QPI 272               // interleaved hi/lo row pitch (bf16) for 128-k rows
#define OPI 144               // interleaved row pitch (bf16) for 64-k rows
#define OPITCH 72             // k_vprep staging pitch (bf16, separate hi/lo)

// -------- scratch (static __device__, allocation-free) --------
__device__ float g_S[(size_t)Ec*Bc*Sc*Sc];           // unnormalized exp scores
__device__ float g_L[Ec*Bc*Sc];                      // row sumexp
__device__ __nv_bfloat16 g_Ai[(size_t)Bc*Sc*Sc*2];   // attn interleaved hi/lo (16 MB)
__device__ __nv_bfloat16 g_vti[Bc*2*DEc*Sc*2];       // V^T interleaved [bs][col][2*t]
// (no g_slot: top-2 recomputed inline)

// ---- bf16 helpers ----
__device__ __forceinline__ unsigned pkbf2(float a, float b) {
    __nv_bfloat162 t = __floats2bfloat162_rn(a, b);
    return *(unsigned*)&t;
}
__device__ __forceinline__ void split2(float x, float y,
                                       unsigned &hi, unsigned &lo) {
    __nv_bfloat16 hx = __float2bfloat16(x), hy = __float2bfloat16(y);
    float rx = x - __bfloat162float(hx), ry = y - __bfloat162float(hy);
    __nv_bfloat162 h; h.x = hx; h.y = hy;
    hi = *(unsigned*)&h;
    lo = pkbf2(rx, ry);
}
__device__ __forceinline__ void split1(float x, __nv_bfloat16 &hi, __nv_bfloat16 &lo) {
    hi = __float2bfloat16(x);
    lo = __float2bfloat16(x - __bfloat162float(hi));
}
__device__ __forceinline__ void mma_bf16(float acc[4],
                                         unsigned a0, unsigned a1, unsigned a2, unsigned a3,
                                         unsigned b0, unsigned b1) {
    asm volatile(
        "mma.sync.aligned.m16n8k16.row.col.f32.bf16.bf16.f32 "
        "{%0,%1,%2,%3}, {%4,%5,%6,%7}, {%8,%9}, {%0,%1,%2,%3};"
        : "+f"(acc[0]), "+f"(acc[1]), "+f"(acc[2]), "+f"(acc[3])
        : "r"(a0), "r"(a1), "r"(a2), "r"(a3), "r"(b0), "r"(b1));
}

// inline top-2 (first-occurrence ties, like lax.top_k)
__device__ __forceinline__ void top2_inline(const float* __restrict__ rp, int b,
                                            int &i1, int &i2) {
    i1 = 0; float v1 = rp[b*Ec];
    #pragma unroll
    for (int e = 1; e < Ec; e++) {
        float v = rp[b*Ec + e];
        if (v > v1) { v1 = v; i1 = e; }
    }
    i2 = -1; float v2 = -INFINITY;
    #pragma unroll
    for (int e = 0; e < Ec; e++) {
        if (e == i1) continue;
        float v = rp[b*Ec + e];
        if (v > v2) { v2 = v; i2 = e; }
    }
}

// ============================================================
// Kz: zero the whole output.
// ============================================================
__global__ void k_zero(float* __restrict__ out) {
    size_t i = ((size_t)blockIdx.x*256 + threadIdx.x)*4;
    *(float4*)(out + i) = make_float4(0.f, 0.f, 0.f, 0.f);
}

// ============================================================
// Kv: V-slice -> transposed interleaved bf16 [bs][col][2*t].
// ============================================================
__global__ void k_vprep(const float* __restrict__ Vg, const float* __restrict__ rp) {
    const int bs = blockIdx.x;            // b*2 + slot
    const int b = bs >> 1, slot = bs & 1;
    int i1, i2; top2_inline(rp, b, i1, i2);
    const int e = slot ? i2 : i1;
    const int t0 = blockIdx.y * 64;
    const int tid = threadIdx.x;

    __shared__ __nv_bfloat16 sh[128*OPITCH];
    __shared__ __nv_bfloat16 sl[128*OPITCH];

    const float* Vb = Vg + ((size_t)b*Sc + t0)*Dc + e*DEc;
    for (int l = tid; l < 2048; l += 256) {
        int t = l >> 5, c4 = (l & 31)*4;
        float4 v = *(const float4*)(Vb + (size_t)t*Dc + c4);
        __nv_bfloat16 h, lo;
        split1(v.x, h, lo); sh[(c4  )*OPITCH + t] = h; sl[(c4  )*OPITCH + t] = lo;
        split1(v.y, h, lo); sh[(c4+1)*OPITCH + t] = h; sl[(c4+1)*OPITCH + t] = lo;
        split1(v.z, h, lo); sh[(c4+2)*OPITCH + t] = h; sl[(c4+2)*OPITCH + t] = lo;
        split1(v.w, h, lo); sh[(c4+3)*OPITCH + t] = h; sl[(c4+3)*OPITCH + t] = lo;
    }
    __syncthreads();
    __nv_bfloat16* D = g_vti + ((size_t)bs*DEc)*2048 + 2*t0;
    for (int l = tid; l < 2048; l += 256) {       // 128 cols x 16 quads of t
        int col = l >> 4, tq = (l & 15)*4;        // t offset within tile
        uint2 hv = *(uint2*)(sh + col*OPITCH + tq);   // {h01, h23}
        uint2 lv = *(uint2*)(sl + col*OPITCH + tq);   // {l01, l23}
        *(uint4*)(D + (size_t)col*2048 + 2*tq) = make_uint4(hv.x, lv.x, hv.y, lv.y);
    }
}

// ============================================================
// K1: scores via bf16-split MMA, interleaved hi/lo smem (LDS.64
// fragment feeds), R14 geometry: 256 thr, 8 warps of 16x32.
// ============================================================
__global__ void k_score(const float* __restrict__ Qg, const float* __restrict__ Kg,
                        const int* __restrict__ em) {
    const int e = blockIdx.z, b = blockIdx.y, s0 = blockIdx.x * 64;
    if (em[e*Bc + b] == 0) return;

    extern __shared__ char smraw[];
    __nv_bfloat16* sQ = (__nv_bfloat16*)smraw;         // 64*272 (interleaved)
    __nv_bfloat16* sK = sQ + 64*QPI;                   // 64*272
    float* sS  = (float*)(sK + 64*QPI);                // 64*68
    float* sLp = sS + 64*68;                           // 2*64

    const int tid = threadIdx.x;
    const int w = tid >> 5, lane = tid & 31;
    const int g = lane >> 2, tig = lane & 3;
    const int rb = (w >> 1) * 16, nb = (w & 1) * 32;

    const float* Qb = Qg + ((size_t)b*Sc + s0)*Dc + e*DEc;
    for (int l = tid; l < 2048; l += 256) {
        int r = l >> 5, c = (l & 31) * 4;
        float4 v = *(const float4*)(Qb + (size_t)r*Dc + c);
        unsigned h01, l01, h23, l23;
        split2(v.x, v.y, h01, l01);
        split2(v.z, v.w, h23, l23);
        *(uint4*)(sQ + r*QPI + c*2) = make_uint4(h01, l01, h23, l23);
    }

    float rs0 = 0.f, rs1 = 0.f;
    float* Srow = g_S + (((size_t)e*Bc + b)*Sc + s0)*Sc;

    for (int t0 = 0; t0 < Sc; t0 += 64) {
        __syncthreads();
        const float* Kb = Kg + ((size_t)b*Sc + t0)*Dc + e*DEc;
        for (int l = tid; l < 2048; l += 256) {
            int r = l >> 5, c = (l & 31) * 4;
            float4 v = *(const float4*)(Kb + (size_t)r*Dc + c);
            unsigned h01, l01, h23, l23;
            split2(v.x, v.y, h01, l01);
            split2(v.z, v.w, h23, l23);
            *(uint4*)(sK + r*QPI + c*2) = make_uint4(h01, l01, h23, l23);
        }
        __syncthreads();

        float acc[4][4] = {};
        #pragma unroll
        for (int kc = 0; kc < 8; kc++) {
            const int koff = kc*32 + tig*4;   // interleaved bf16 offset
            uint2 a0 = *(uint2*)(sQ + (rb+g  )*QPI + koff);        // {ah0, al0}
            uint2 a1 = *(uint2*)(sQ + (rb+g+8)*QPI + koff);        // {ah1, al1}
            uint2 a2 = *(uint2*)(sQ + (rb+g  )*QPI + koff + 16);   // {ah2, al2}
            uint2 a3 = *(uint2*)(sQ + (rb+g+8)*QPI + koff + 16);   // {ah3, al3}
            #pragma unroll
            for (int ns = 0; ns < 4; ns++) {
                const int n = nb + ns*8 + g;
                uint2 b0 = *(uint2*)(sK + n*QPI + koff);           // {bh0, bl0}
                uint2 b1 = *(uint2*)(sK + n*QPI + koff + 16);      // {bh1, bl1}
                mma_bf16(acc[ns], a0.x, a1.x, a2.x, a3.x, b0.x, b1.x);
                mma_bf16(acc[ns], a0.x, a1.x, a2.x, a3.x, b0.y, b1.y);
                mma_bf16(acc[ns], a0.y, a1.y, a2.y, a3.y, b0.x, b1.x);
            }
        }

        #pragma unroll
        for (int ns = 0; ns < 4; ns++) {
            float p0 = __expf(acc[ns][0]*SCALEF);
            float p1 = __expf(acc[ns][1]*SCALEF);
            float p2 = __expf(acc[ns][2]*SCALEF);
            float p3 = __expf(acc[ns][3]*SCALEF);
            rs0 += p0 + p1;
            rs1 += p2 + p3;
            const int col = nb + ns*8 + tig*2;
            *(float2*)(sS + (rb+g  )*68 + col) = make_float2(p0, p1);
            *(float2*)(sS + (rb+g+8)*68 + col) = make_float2(p2, p3);
        }
        __syncthreads();

        for (int l = tid; l < 1024; l += 256) {
            int r = l >> 4, c4 = l & 15;
            *(float4*)(Srow + (size_t)r*Sc + t0 + c4*4) = *(const float4*)(sS + r*68 + c4*4);
        }
    }

    rs0 += __shfl_xor_sync(0xffffffffu, rs0, 1);
    rs0 += __shfl_xor_sync(0xffffffffu, rs0, 2);
    rs1 += __shfl_xor_sync(0xffffffffu, rs1, 1);
    rs1 += __shfl_xor_sync(0xffffffffu, rs1, 2);
    if (tig == 0) {
        sLp[(w & 1)*64 + rb + g]     = rs0;
        sLp[(w & 1)*64 + rb + g + 8] = rs1;
    }
    __syncthreads();
    if (tid < 64)
        g_L[(e*Bc + b)*Sc + s0 + tid] = sLp[tid] + sLp[64 + tid];
}

// ============================================================
// K2: attn = sum_e mask*p/L, emitted interleaved hi/lo. 2 rows/block.
// ============================================================
__global__ void k_combine(const int* __restrict__ em) {
    const int blk = blockIdx.x;                 // b*512 + spair
    const int b = blk >> 9, s0 = (blk & 511)*2;
    const int tid = threadIdx.x;

    float4 acc0 = make_float4(0.f, 0.f, 0.f, 0.f);
    float4 acc1 = make_float4(0.f, 0.f, 0.f, 0.f);
    #pragma unroll
    for (int e = 0; e < Ec; e++) {
        if (em[e*Bc + b] == 0) continue;
        int eb = e*Bc + b;
        float iL0 = 1.0f / g_L[(size_t)eb*Sc + s0];
        float iL1 = 1.0f / g_L[(size_t)eb*Sc + s0 + 1];
        const float* base = g_S + ((size_t)eb*Sc + s0)*Sc + tid*4;
        float4 v0 = *(const float4*)(base);
        float4 v1 = *(const float4*)(base + Sc);
        acc0.x += v0.x*iL0; acc0.y += v0.y*iL0; acc0.z += v0.z*iL0; acc0.w += v0.w*iL0;
        acc1.x += v1.x*iL1; acc1.y += v1.y*iL1; acc1.z += v1.z*iL1; acc1.w += v1.w*iL1;
    }
    unsigned h01, l01, h23, l23;
    size_t ob = ((size_t)b*Sc + s0)*2048 + tid*8;   // interleaved row length 2048 bf16
    split2(acc0.x, acc0.y, h01, l01);
    split2(acc0.z, acc0.w, h23, l23);
    *(uint4*)(g_Ai + ob) = make_uint4(h01, l01, h23, l23);
    split2(acc1.x, acc1.y, h01, l01);
    split2(acc1.z, acc1.w, h23, l23);
    *(uint4*)(g_Ai + ob + 2048) = make_uint4(h01, l01, h23, l23);
}

// ============================================================
// K3: out = attn @ V-slice, interleaved smem, R12/R14 geometry:
// 256 thr, 8 warps (2 row x 4 col), 32-row tiles, 256 working blocks.
// ============================================================
__global__ void k_out(const float* __restrict__ rp, float* __restrict__ out) {
    const int b = blockIdx.x, s0 = blockIdx.y*32, slot = blockIdx.z;
    int i1, i2; top2_inline(rp, b, i1, i2);
    const int e = slot ? i2 : i1;
    const int bs = b*2 + slot;

    extern __shared__ __nv_bfloat16 smb[];
    __nv_bfloat16* sA = smb;                   // 32*144 (interleaved)
    __nv_bfloat16* sV = sA + 32*OPI;           // 128*144

    const int tid = threadIdx.x;
    const int w = tid >> 5, lane = tid & 31;
    const int g = lane >> 2, tig = lane & 3;
    const int rb = (w & 1) * 16, nb = (w >> 1) * 32;

    float acc[4][4] = {};

    for (int t0 = 0; t0 < Sc; t0 += 64) {
        __syncthreads();
        const __nv_bfloat16* Ab = g_Ai + ((size_t)b*Sc + s0)*2048 + 2*t0;
        for (int l = tid; l < 512; l += 256) {       // 32 rows x 16 uint4
            int r = l >> 4, c = (l & 15)*8;
            *(uint4*)(sA + r*OPI + c) = *(const uint4*)(Ab + (size_t)r*2048 + c);
        }
        const __nv_bfloat16* Vb = g_vti + ((size_t)bs*DEc)*2048 + 2*t0;
        for (int l = tid; l < 2048; l += 256) {      // 128 cols x 16 uint4
            int col = l >> 4, c = (l & 15)*8;
            *(uint4*)(sV + col*OPI + c) = *(const uint4*)(Vb + (size_t)col*2048 + c);
        }
        __syncthreads();

        #pragma unroll
        for (int ks = 0; ks < 4; ks++) {
            const int koff = ks*32 + tig*4;
            uint2 a0 = *(uint2*)(sA + (rb+g  )*OPI + koff);
            uint2 a1 = *(uint2*)(sA + (rb+g+8)*OPI + koff);
            uint2 a2 = *(uint2*)(sA + (rb+g  )*OPI + koff + 16);
            uint2 a3 = *(uint2*)(sA + (rb+g+8)*OPI + koff + 16);
            #pragma unroll
            for (int ns = 0; ns < 4; ns++) {
                const int n = nb + ns*8 + g;
                uint2 b0 = *(uint2*)(sV + n*OPI + koff);
                uint2 b1 = *(uint2*)(sV + n*OPI + koff + 16);
                mma_bf16(acc[ns], a0.x, a1.x, a2.x, a3.x, b0.x, b1.x);
                mma_bf16(acc[ns], a0.x, a1.x, a2.x, a3.x, b0.y, b1.y);
                mma_bf16(acc[ns], a0.y, a1.y, a2.y, a3.y, b0.x, b1.x);
            }
        }
    }

    float* O = out + ((size_t)b*Sc + s0)*Dc + e*DEc;
    #pragma unroll
    for (int ns = 0; ns < 4; ns++) {
        const int nc = nb + ns*8 + tig*2;
        *(float2*)(O + (size_t)(rb+g  )*Dc + nc) = make_float2(acc[ns][0], acc[ns][1]);
        *(float2*)(O + (size_t)(rb+g+8)*Dc + nc) = make_float2(acc[ns][2], acc[ns][3]);
    }
}

// ============================================================
extern "C" void kernel_launch(void* const* d_in, const int* in_sizes, int n_in,
                              void* d_out, int out_size) {
    const float* Q  = (const float*)d_in[0];
    const float* K  = (const float*)d_in[1];
    const float* V  = (const float*)d_in[2];
    const float* rp = (const float*)d_in[3];
    const int*   em = (const int*)  d_in[4];
    float* out = (float*)d_out;

    const int smem_score = 2*64*QPI*2 + (64*68 + 2*64)*4;   // 87552 B (same as R14)
    const int smem_out   = (32 + 128)*OPI*2;                // 46080 B (same as R14)
    cudaFuncSetAttribute(k_score, cudaFuncAttributeMaxDynamicSharedMemorySize, smem_score);
    cudaFuncSetAttribute(k_out,   cudaFuncAttributeMaxDynamicSharedMemorySize, smem_out);

    k_zero   <<<(Bc*Sc*Dc)/(256*4), 256>>>(out);
    k_vprep  <<<dim3(Bc*2, 16), 256>>>(V, rp);
    k_score  <<<dim3(Sc/64, Bc, Ec), 256, smem_score>>>(Q, K, em);
    k_combine<<<Bc*Sc/2, 256>>>(em);
    k_out    <<<dim3(Bc, Sc/32, 2), 256, smem_out>>>(rp, out);
}